// round 17
// baseline (speedup 1.0000x reference)
#include <cuda_runtime.h>
#include <math.h>

#define NB     64
#define TT     1024
#define ML     256
#define PP     (TT - 1)
#define NTHR   128          // 4 warps, all striding over both groups' blocks
#define CPB    16           // CTAs per batch; CTA owns groups {part, 31-part}
#define NBLK   (NB * CPB)   // 1024 CTAs
#define GL     8            // lags per group

// Packed f32x2 ops (Blackwell FFMA2/FADD2/FMUL2 — PTX-only)
#define FMA_F32X2(out, a, b, c) \
    asm("fma.rn.f32x2 %0, %1, %2, %3;" : "=l"(out) : "l"(a), "l"(b), "l"(c))
#define ADD_F32X2(out, a, b) \
    asm("add.rn.f32x2 %0, %1, %2;" : "=l"(out) : "l"(a), "l"(b))
#define MUL_F32X2(out, a, b) \
    asm("mul.rn.f32x2 %0, %1, %2;" : "=l"(out) : "l"(a), "l"(b))

#define NEG1_X2 0xBF800000BF800000ULL   // (-1.f, -1.f)

__device__ __forceinline__ float unpack_sum(unsigned long long v) {
    float lo = __uint_as_float((unsigned int)v);
    float hi = __uint_as_float((unsigned int)(v >> 32));
    return lo + hi;
}

// Two-level reduction state (zero-initialized; counters self-reset).
__device__ double g_part[NBLK][3];     // per-CTA [Sm, S1, S2]
__device__ float  g_spt[NB];           // per-batch per_traj
__device__ unsigned int g_bcount[NB];  // per-batch arrival counters
__device__ unsigned int g_count;       // global arrival counter

// lengths may arrive as int64 or int32 (JAX x64 flag dependent).
__device__ __forceinline__ int get_len(const void* Lp, int b) {
    const long long* L64 = (const long long*)Lp;
    long long v0 = L64[0];
    if (v0 >= 1 && v0 <= (long long)TT) return (int)L64[b];
    return ((const int*)Lp)[b];
}

// One 64-position block for one 8-lag group, packed f32x2 math.
__device__ __forceinline__ void do_block(const ulonglong2* __restrict__ sh8,
                                         int p, int l0,
                                         unsigned long long* acc2) {
    ulonglong2 aq = sh8[p >> 1];                 // points p, p+1 (packed)
    const int k0 = (p + l0 - 1) >> 1;            // l0 odd -> even window start
    ulonglong2 Q0 = sh8[k0],     Q1 = sh8[k0 + 1], Q2 = sh8[k0 + 2];
    ulonglong2 Q3 = sh8[k0 + 3], Q4 = sh8[k0 + 4];

    unsigned long long w[10];                    // window pos l0-1 .. l0+8
    w[0]=Q0.x; w[1]=Q0.y; w[2]=Q1.x; w[3]=Q1.y; w[4]=Q2.x;
    w[5]=Q2.y; w[6]=Q3.x; w[7]=Q3.y; w[8]=Q4.x; w[9]=Q4.y;

    unsigned long long na0, na1;
    MUL_F32X2(na0, aq.x, NEG1_X2);
    MUL_F32X2(na1, aq.y, NEG1_X2);

    #pragma unroll
    for (int j = 0; j < GL; j++) {
        unsigned long long d0, d1;
        ADD_F32X2(d0, w[j + 1], na0);
        FMA_F32X2(acc2[j], d0, d0, acc2[j]);
        ADD_F32X2(d1, w[j + 2], na1);
        FMA_F32X2(acc2[j], d1, d1, acc2[j]);
    }
}

// ---------------------------------------------------------------------------
// Warp-balanced layout: CTA owns complementary groups A=part, B=31-part
// (n_A + n_B ~ const), and ALL 4 warps stride (by 4) over both groups'
// position blocks -> every warp in the grid does ~equal work; the wave
// finishes coherently. f32x2 inner math; two-level cross-CTA reduction.
// ---------------------------------------------------------------------------
__global__ void __launch_bounds__(NTHR, 7)
fused_kernel(const float* __restrict__ traj,
             const void*  __restrict__ lengths,
             const float* __restrict__ alpha_pred,
             float* __restrict__ out)
{
    __shared__ float4 sh4[TT / 2];     // positions 2k,2k+1 per float4
    __shared__ float  sacc[2][4][GL];  // [group][warp][lag]

    const int blk  = blockIdx.x;
    const int b    = blk >> 4;         // batch
    const int part = blk & 15;

    const int   len   = get_len(lengths, b);
    const float alpha = alpha_pred[b];

    const float2*     sh  = (const float2*)sh4;
    const ulonglong2* sh8 = (const ulonglong2*)sh4;

    const float4* rowq = (const float4*)(traj + (size_t)b * TT * 2);
    #pragma unroll
    for (int i = threadIdx.x; i < TT / 2; i += NTHR) sh4[i] = rowq[i];
    __syncthreads();

    const int warp = threadIdx.x >> 5;
    const int lane = threadIdx.x & 31;

    const int gA  = part;              // groups 0..15 (big n)
    const int gB  = 31 - part;         // groups 16..31 (small n)
    const int l0A = 1 + GL * gA;       // odd
    const int l0B = 1 + GL * gB;       // odd

    int nminA = len - (l0A + GL - 1);
    if (nminA < 0) nminA = 0;
    if (nminA > PP) nminA = PP;
    int nmaxA = len - l0A;
    if (nmaxA < 0) nmaxA = 0;
    if (nmaxA > PP) nmaxA = PP;
    int nminB = len - (l0B + GL - 1);
    if (nminB < 0) nminB = 0;
    if (nminB > PP) nminB = PP;
    int nmaxB = len - l0B;
    if (nmaxB < 0) nmaxB = 0;
    if (nmaxB > PP) nmaxB = PP;

    unsigned long long accA2[GL], accB2[GL];
    #pragma unroll
    for (int j = 0; j < GL; j++) { accA2[j] = 0ULL; accB2[j] = 0ULL; }

    const int imaxA = nminA >> 6;
    const int imaxB = nminB >> 6;

    // --- main region: blocks strided by 4 across warps, both groups ---
    for (int i = warp; i < imaxA; i += 4)
        do_block(sh8, (i << 6) + (lane << 1), l0A, accA2);
    for (int i = warp; i < imaxB; i += 4)
        do_block(sh8, (i << 6) + (lane << 1), l0B, accB2);

    // --- unpack packed accumulators -> scalar ---
    float accA[GL], accB[GL];
    #pragma unroll
    for (int j = 0; j < GL; j++) {
        accA[j] = unpack_sum(accA2[j]);
        accB[j] = unpack_sum(accB2[j]);
    }

    // --- masked tails in parallel: warp 0 -> group A, warp 1 -> group B ---
    if (warp == 0) {
        for (int p = (imaxA << 6) + lane; p < nmaxA; p += 32) {
            float2 a = sh[p];
            #pragma unroll
            for (int j = 0; j < GL; j++) {
                int nj = len - (l0A + j);
                if (nj > PP) nj = PP;
                if (p < nj) {
                    float2 e = sh[p + l0A + j];
                    float dx = e.x - a.x, dy = e.y - a.y;
                    accA[j] += dx * dx + dy * dy;
                }
            }
        }
    }
    if (warp == 1) {
        for (int p = (imaxB << 6) + lane; p < nmaxB; p += 32) {
            float2 a = sh[p];
            #pragma unroll
            for (int j = 0; j < GL; j++) {
                int nj = len - (l0B + j);
                if (nj > PP) nj = PP;
                if (p < nj) {
                    float2 e = sh[p + l0B + j];
                    float dx = e.x - a.x, dy = e.y - a.y;
                    accB[j] += dx * dx + dy * dy;
                }
            }
        }
    }

    // --- warp reduce all 16 accs, stash per-warp sums ---
    #pragma unroll
    for (int j = 0; j < GL; j++) {
        #pragma unroll
        for (int o = 16; o > 0; o >>= 1) {
            accA[j] += __shfl_xor_sync(0xffffffffu, accA[j], o);
            accB[j] += __shfl_xor_sync(0xffffffffu, accB[j], o);
        }
    }
    if (lane == 0) {
        #pragma unroll
        for (int j = 0; j < GL; j++) {
            sacc[0][warp][j] = accA[j];
            sacc[1][warp][j] = accB[j];
        }
    }
    __syncthreads();

    // ======================= tail: warp 0 only =======================
    if (warp == 0) {
        double sm = 0.0, s1 = 0.0, s2 = 0.0;
        if (lane < 16) {
            const int gs  = lane >> 3;                    // 0 -> A, 1 -> B
            const int jj  = lane & 7;
            const int grp = gs ? gB : gA;
            const int lag = 1 + GL * grp + jj;
            int nj = len - lag;
            if (nj < 0) nj = 0;
            if (nj > PP) nj = PP;
            const float tot = sacc[gs][0][jj] + sacc[gs][1][jj]
                            + sacc[gs][2][jj] + sacc[gs][3][jj];
            const float msd = (nj > 0) ? tot / (float)nj : 0.f;
            const float r = logf(msd + 1e-8f) - alpha * logf((float)lag);
            if (len > lag) {
                sm = 1.0; s1 = (double)r; s2 = (double)r * (double)r;
            }
        }
        #pragma unroll
        for (int o = 16; o > 0; o >>= 1) {
            sm += __shfl_xor_sync(0xffffffffu, sm, o);
            s1 += __shfl_xor_sync(0xffffffffu, s1, o);
            s2 += __shfl_xor_sync(0xffffffffu, s2, o);
        }

        unsigned int oldb = 0u;
        if (lane == 0) {
            g_part[blk][0] = sm; g_part[blk][1] = s1; g_part[blk][2] = s2;
            __threadfence();
            oldb = atomicAdd(&g_bcount[b], 1u);
        }
        oldb = __shfl_sync(0xffffffffu, oldb, 0);

        if (oldb == CPB - 1) {
            // ---- per-batch last CTA: reduce 16 partials (lane-parallel) ----
            __threadfence();
            double Sm = 0.0, S1 = 0.0, S2 = 0.0;
            if (lane < CPB) {
                const int idx = b * CPB + lane;
                Sm = g_part[idx][0];
                S1 = g_part[idx][1];
                S2 = g_part[idx][2];
            }
            #pragma unroll
            for (int o = 16; o > 0; o >>= 1) {
                Sm += __shfl_xor_sync(0xffffffffu, Sm, o);
                S1 += __shfl_xor_sync(0xffffffffu, S1, o);
                S2 += __shfl_xor_sync(0xffffffffu, S2, o);
            }
            unsigned int oldg = 0u;
            if (lane == 0) {
                double denom = (Sm > 1.0) ? Sm : 1.0;
                double I = S1 / denom;
                double pt = (S2 - 2.0 * I * S1 + I * I * Sm) / denom;
                g_spt[b] = (float)pt;
                g_bcount[b] = 0;             // reset for next replay
                __threadfence();
                oldg = atomicAdd(&g_count, 1u);
            }
            oldg = __shfl_sync(0xffffffffu, oldg, 0);

            if (oldg == NB - 1) {
                // ---- global last: reduce 64 per-batch values ----
                __threadfence();
                float v = g_spt[lane] + g_spt[lane + 32];
                #pragma unroll
                for (int o = 16; o > 0; o >>= 1)
                    v += __shfl_xor_sync(0xffffffffu, v, o);
                if (lane == 0) {
                    g_count = 0;             // reset for next replay
                    __threadfence();
                    out[0] = v / (float)NB;
                }
            }
        }
    }
}

// ---------------------------------------------------------------------------
// Inputs: [0] alpha_pred f32[64], [1] trajectory f32[64,1024,2],
// [2] lengths int64/int32[64]. Output: 1 float.
// ---------------------------------------------------------------------------
extern "C" void kernel_launch(void* const* d_in, const int* in_sizes, int n_in,
                              void* d_out, int out_size)
{
    const float* alpha = (const float*)d_in[0];
    const float* traj  = (const float*)d_in[1];
    const void*  lens  = d_in[2];
    float* out = (float*)d_out;

    fused_kernel<<<NBLK, NTHR>>>(traj, lens, alpha, out);
}